// round 14
// baseline (speedup 1.0000x reference)
#include <cuda_runtime.h>
#include <cuda_bf16.h>
#include <cstdint>

// ---------------- problem constants ----------------
#define M_CANDS 131072
#define N_ROWS  2048
#define DIM     64
#define KSEL    11                 // k+1 smallest; smallest (self) dropped later

// ---------------- tiling / ragged static decomposition ----------------
#define ROWS_CTA 256                     // x rows per CTA (16 warps x 16 rows)
#define ROWTILES (N_ROWS / ROWS_CTA)     // 8
#define TN       256                     // candidates per smem tile
#define NTILES   (M_CANDS / TN)          // 512 tile-columns per rowtile
#define THREADS  512
#define GRID_MAIN 148                    // rowtiles 0-3: 19 CTAs, 4-7: 18 CTAs
#define MAXL     19                      // max lists per row
#define NTS      5                       // SIMT tiles per CTA (nt is 26..29)
#define TILE_BYTES (TN * 128)            // 32768
#define SIMT_BYTES 8192                  // 64 cands * 128B per slot
#define BN_BYTES   (TN * 4)              // 1024
#define SBN_BYTES  256                   // 64 norms

// ---------------- smem layout (bytes) ----------------
#define SM_MBAR  0                       // 3 mbarriers
#define SM_B     1024
#define SLOT_STRIDE (TILE_BYTES + SIMT_BYTES)     // 40960; simt at +32768
#define SM_BN    (SM_B + 3 * SLOT_STRIDE)         // 123904
#define SM_SBN   (SM_BN + 3 * BN_BYTES)           // 126976
#define SMEM_TOTAL (SM_SBN + 3 * SBN_BYTES)       // 127744

#define POS_INF __int_as_float(0x7f800000)
#define NEG_INF __int_as_float(0xff800000)

// ---------------- device globals (allocation-free scratch) ----------------
__device__ __align__(128) __nv_bfloat16 g_bbf[(size_t)M_CANDS * DIM]; // -2*buf, bf16, tile-swizzled
__device__ __align__(16)  __nv_bfloat16 g_xbf[(size_t)N_ROWS * DIM];
__device__ __align__(16)  float g_bnorm[M_CANDS];
__device__ __align__(16)  float g_xnorm[N_ROWS];
__device__ __align__(16)  float g_partial[(size_t)N_ROWS * MAXL * KSEL];

// ---------------- helpers ----------------
__device__ __forceinline__ uint32_t smem_u32(const void* p) {
    return (uint32_t)__cvta_generic_to_shared(p);
}
#define SWZ128(off) ((off) ^ (((off) >> 3) & 0x70))

#define MBARRIER_INIT(mbar, cnt) \
    asm volatile("mbarrier.init.shared.b64 [%0], %1;" \
                 :: "r"((uint32_t)(mbar)), "r"((uint32_t)(cnt)) : "memory")
#define MBARRIER_EXPECT_TX(mbar, bytes) \
    asm volatile("mbarrier.arrive.expect_tx.shared.b64 _, [%0], %1;" \
                 :: "r"((uint32_t)(mbar)), "r"((uint32_t)(bytes)) : "memory")
#define MBARRIER_WAIT_PARITY(mbar, parity) do {                                   \
    uint32_t _m = (uint32_t)(mbar); uint32_t _p = (uint32_t)(parity);             \
    asm volatile("{\n\t.reg .pred P1;\n\t"                                        \
        "WAIT_LOOP_%=:\n\t"                                                       \
        "mbarrier.try_wait.parity.acquire.cta.shared::cta.b64 P1, [%0], %1, 0x989680;\n\t" \
        "@P1 bra.uni WAIT_DONE_%=;\n\t"                                           \
        "bra.uni WAIT_LOOP_%=;\n\t"                                               \
        "WAIT_DONE_%=:\n\t}" :: "r"(_m), "r"(_p) : "memory");                     \
} while (0)

__device__ __forceinline__ void bulk_g2s(uint32_t dst, const void* src,
                                         uint32_t bytes, uint32_t mbar) {
    asm volatile(
        "cp.async.bulk.shared::cluster.global.mbarrier::complete_tx::bytes "
        "[%0], [%1], %2, [%3];"
        :: "r"(dst), "l"(__cvta_generic_to_global(src)), "r"(bytes), "r"(mbar)
        : "memory");
}

// ldmatrix x4: 4 8x8 b16 matrices; lane supplies one 16B row address
__device__ __forceinline__ void ldsm4(uint32_t* r, uint32_t addr) {
    asm volatile("ldmatrix.sync.aligned.m8n8.x4.shared.b16 {%0,%1,%2,%3}, [%4];"
                 : "=r"(r[0]), "=r"(r[1]), "=r"(r[2]), "=r"(r[3]) : "r"(addr));
}

// m16n8k16 row.col bf16 -> f32, D += A*B (D aliases C)
__device__ __forceinline__ void mma16816(float c[4], const uint32_t a[4],
                                         uint32_t b0, uint32_t b1) {
    asm volatile(
        "mma.sync.aligned.m16n8k16.row.col.f32.bf16.bf16.f32 "
        "{%0,%1,%2,%3}, {%4,%5,%6,%7}, {%8,%9}, {%0,%1,%2,%3};"
        : "+f"(c[0]), "+f"(c[1]), "+f"(c[2]), "+f"(c[3])
        : "r"(a[0]), "r"(a[1]), "r"(a[2]), "r"(a[3]), "r"(b0), "r"(b1));
}

#define HFMA2BF(acc, x, b) \
    asm("fma.rn.bf16x2 %0, %1, %2, %0;" : "+r"(acc) : "r"(x), "r"(b))

// register-resident ascending insert; v > h[10] is a no-op
__device__ __forceinline__ void bubble_insert(float* h, float v) {
#pragma unroll
    for (int j = 0; j < KSEL; ++j) {
        float lo = fminf(h[j], v);
        v = fmaxf(h[j], v);
        h[j] = lo;
    }
}

// merge my ascending 11-list with lane^mask's; keep 11 smallest, ascending
__device__ __forceinline__ void merge11(float h[KSEL], int mask) {
    float b[KSEL];
#pragma unroll
    for (int j = 0; j < KSEL; ++j) b[j] = __shfl_xor_sync(0xffffffffu, h[j], mask);
    float c[16];
#pragma unroll
    for (int i = 0; i < 5; ++i) c[i] = NEG_INF;
#pragma unroll
    for (int i = 0; i < KSEL; ++i) c[5 + i] = fminf(h[i], b[10 - i]);
#pragma unroll
    for (int d = 8; d >= 1; d >>= 1)
#pragma unroll
        for (int i = 0; i < 16; ++i)
            if ((i & d) == 0) {
                float lo = fminf(c[i], c[i | d]);
                float hi = fmaxf(c[i], c[i | d]);
                c[i] = lo; c[i | d] = hi;
            }
#pragma unroll
    for (int i = 0; i < KSEL; ++i) h[i] = c[5 + i];
}

// ---------------- prep kernels ----------------
__global__ void prep_buf_kernel(const float* __restrict__ buf) {
    int c = blockIdx.x * 256 + threadIdx.x;
    const float4* s = reinterpret_cast<const float4*>(buf) + (size_t)c * 16;
    uint4 pk[8];
    uint32_t* pw = reinterpret_cast<uint32_t*>(pk);
    float n = 0.f;
#pragma unroll
    for (int q = 0; q < 16; ++q) {
        float4 v = s[q];
        n = fmaf(v.x, v.x, n); n = fmaf(v.y, v.y, n);
        n = fmaf(v.z, v.z, n); n = fmaf(v.w, v.w, n);
        __nv_bfloat162 a = __floats2bfloat162_rn(-2.f * v.x, -2.f * v.y);
        __nv_bfloat162 b = __floats2bfloat162_rn(-2.f * v.z, -2.f * v.w);
        pw[2 * q]     = reinterpret_cast<uint32_t&>(a);
        pw[2 * q + 1] = reinterpret_cast<uint32_t&>(b);
    }
    char* blk = reinterpret_cast<char*>(g_bbf) + (size_t)(c >> 8) * TILE_BYTES;
    uint32_t r = (uint32_t)(c & 255);
#pragma unroll
    for (int q = 0; q < 8; ++q)
        *reinterpret_cast<uint4*>(blk + SWZ128(r * 128 + q * 16)) = pk[q];
    g_bnorm[c] = n;
}

__global__ void prep_x_kernel(const float* __restrict__ x) {
    int c = blockIdx.x * 256 + threadIdx.x;
    const float4* s = reinterpret_cast<const float4*>(x) + (size_t)c * 16;
    uint4 pk[8];
    uint32_t* pw = reinterpret_cast<uint32_t*>(pk);
    float n = 0.f;
#pragma unroll
    for (int q = 0; q < 16; ++q) {
        float4 v = s[q];
        n = fmaf(v.x, v.x, n); n = fmaf(v.y, v.y, n);
        n = fmaf(v.z, v.z, n); n = fmaf(v.w, v.w, n);
        __nv_bfloat162 a = __floats2bfloat162_rn(v.x, v.y);
        __nv_bfloat162 b = __floats2bfloat162_rn(v.z, v.w);
        pw[2 * q]     = reinterpret_cast<uint32_t&>(a);
        pw[2 * q + 1] = reinterpret_cast<uint32_t&>(b);
    }
    uint4* dst = reinterpret_cast<uint4*>(g_xbf) + (size_t)c * 8;
#pragma unroll
    for (int i = 0; i < 8; ++i) dst[i] = pk[i];
    g_xnorm[c] = n;
}

// ---------------- main fused dual-pipe GEMM + top-k kernel ----------------
extern __shared__ char smem[];

__global__ void __launch_bounds__(THREADS, 1)
pbe_mma_kernel() {
    const int tid  = threadIdx.x;
    const int lane = tid & 31;
    const int w    = tid >> 5;           // 0..15
    const int g    = lane >> 2;          // 0..7
    const int tig  = lane & 3;           // 0..3

    // ---- ragged static assignment: (rowtile, contiguous tile range) ----
    int rt, c, nc;
    {
        const int b = blockIdx.x;        // 0..147
        if (b < 76) { rt = b / 19; c = b - rt * 19; nc = 19; }
        else { int b2 = b - 76; rt = 4 + b2 / 18; c = b2 - (rt - 4) * 18; nc = 18; }
    }
    const int t0 = (NTILES * c) / nc;
    const int nt = (NTILES * (c + 1)) / nc - t0;   // 26..29 tiles
    const int ntt = nt - NTS;                       // tensor slots: 21..24
    const int row_base = rt * ROWS_CTA + w * 16;

    const uint32_t sbase = smem_u32(smem);
    const uint32_t mb0   = sbase + SM_MBAR;

    // ---- A fragments: 1 m-block (16 rows) per warp, persistent ----
    uint32_t afr[4][4];
    {
        const uint32_t* x0 = reinterpret_cast<const uint32_t*>(
            g_xbf + (size_t)(row_base + g) * DIM);
        const uint32_t* x1 = reinterpret_cast<const uint32_t*>(
            g_xbf + (size_t)(row_base + g + 8) * DIM);
#pragma unroll
        for (int kc = 0; kc < 4; ++kc) {
            afr[kc][0] = x0[kc * 8 + tig];
            afr[kc][1] = x1[kc * 8 + tig];
            afr[kc][2] = x0[kc * 8 + tig + 4];
            afr[kc][3] = x1[kc * 8 + tig + 4];
        }
    }

    // ---- SIMT co-path x slice: row (tig<2 ? g : g+8), dim-half (tig&1) ----
    uint32_t xs[16];
    {
        const int srow = row_base + ((tig < 2) ? g : g + 8);
        const uint32_t* xr = reinterpret_cast<const uint32_t*>(
            g_xbf + (size_t)srow * DIM) + (tig & 1) * 16;
#pragma unroll
        for (int i = 0; i < 16; ++i) xs[i] = xr[i];
    }
    const uint32_t half64 = (uint32_t)(tig & 1) * 64;

    // ---- per-lane ldmatrix offsets (swizzle XOR applied last, no carries) ----
    const uint32_t l8  = (uint32_t)(lane & 7);
    const uint32_t qof = (uint32_t)((lane >> 3) * 16);
    const uint32_t sw  = l8 << 4;
    const uint32_t lm_off0 = l8 * 128 + (qof ^ sw);          // k bytes 0..63
    const uint32_t lm_off1 = l8 * 128 + ((qof + 64) ^ sw);   // k bytes 64..127

    // ---- mbarriers + prologue staging ----
    if (tid == 0) {
        MBARRIER_INIT(mb0 + 0,  1);
        MBARRIER_INIT(mb0 + 8,  1);
        MBARRIER_INIT(mb0 + 16, 1);
    }
    __syncthreads();

    auto issue = [&](int t) {            // thread 0 only
        int s = t % 3;
        uint32_t bar = mb0 + s * 8;
        uint32_t cb = (uint32_t)(t0 + t) * TN;   // tensor candidate index
        const int sact = t < NTS * 4;
        MBARRIER_EXPECT_TX(bar, TILE_BYTES + BN_BYTES
                                + (sact ? (SIMT_BYTES + SBN_BYTES) : 0));
        bulk_g2s(sbase + SM_B + s * SLOT_STRIDE,
                 reinterpret_cast<const char*>(g_bbf) + (size_t)cb * 128,
                 TILE_BYTES, bar);
        bulk_g2s(sbase + SM_BN + s * BN_BYTES, g_bnorm + cb, BN_BYTES, bar);
        if (sact) {
            uint32_t sc = (uint32_t)(t0 + ntt) * TN + (uint32_t)t * 64;
            bulk_g2s(sbase + SM_B + s * SLOT_STRIDE + TILE_BYTES,
                     reinterpret_cast<const char*>(g_bbf) + (size_t)sc * 128,
                     SIMT_BYTES, bar);
            bulk_g2s(sbase + SM_SBN + s * SBN_BYTES, g_bnorm + sc, SBN_BYTES, bar);
        }
    };
    if (tid == 0) { issue(0); issue(1); }

    // ---- top-11 lists for this thread's 2 rows ----
    float h0[KSEL], h1[KSEL];
#pragma unroll
    for (int j = 0; j < KSEL; ++j) { h0[j] = POS_INF; h1[j] = POS_INF; }

    uint32_t ph[3] = {0, 0, 0};

    for (int t = 0; t < ntt; ++t) {
        const int slot = t % 3;
        __syncthreads();                 // all warps finished compute(t-1)
        if (t + 2 < ntt && tid == 0) issue(t + 2);
        MBARRIER_WAIT_PARITY(mb0 + slot * 8, ph[slot]);
        ph[slot] ^= 1;

        const uint32_t tb0 = sbase + SM_B + slot * SLOT_STRIDE + lm_off0;
        const uint32_t tb1 = sbase + SM_B + slot * SLOT_STRIDE + lm_off1;
        const float*   bns = reinterpret_cast<const float*>(
                                 smem + SM_BN + slot * BN_BYTES) + tig * 2;
        const uint32_t sb  = sbase + SM_B + slot * SLOT_STRIDE + TILE_BYTES;
        const float*   sbn = reinterpret_cast<const float*>(
                                 smem + SM_SBN + slot * SBN_BYTES);
        const int sact = t < NTS * 4;

        // k-half double-buffered fragments: fA = kc0/1, fB = kc2/3
        uint32_t fA[2][4], fB[2][4];
        ldsm4(&fA[0][0], tb0);
        ldsm4(&fA[1][0], tb0 + 1024);

#pragma unroll
        for (int p = 0; p < 16; ++p) {
            // prefetch k-half 1 of this nb pair
            ldsm4(&fB[0][0], tb1 + p * 2048);
            ldsm4(&fB[1][0], tb1 + p * 2048 + 1024);

            float acc[2][4];
#pragma unroll
            for (int q = 0; q < 2; ++q) {
                const float2 bnv = *reinterpret_cast<const float2*>(
                    &bns[(p * 2 + q) * 8]);
                acc[q][0] = bnv.x; acc[q][1] = bnv.y;
                acc[q][2] = bnv.x; acc[q][3] = bnv.y;
            }
            mma16816(acc[0], afr[0], fA[0][0], fA[0][1]);
            mma16816(acc[1], afr[0], fA[1][0], fA[1][1]);
            mma16816(acc[0], afr[1], fA[0][2], fA[0][3]);
            mma16816(acc[1], afr[1], fA[1][2], fA[1][3]);

            // prefetch k-half 0 of next nb pair
            if (p < 15) {
                ldsm4(&fA[0][0], tb0 + (p + 1) * 2048);
                ldsm4(&fA[1][0], tb0 + (p + 1) * 2048 + 1024);
            }
            mma16816(acc[0], afr[2], fB[0][0], fB[0][1]);
            mma16816(acc[1], afr[2], fB[1][0], fB[1][1]);
            mma16816(acc[0], afr[3], fB[0][2], fB[0][3]);
            mma16816(acc[1], afr[3], fB[1][2], fB[1][3]);

            // acc IS the distance (bn - 2*dot); |x|^2 deferred
#pragma unroll
            for (int q = 0; q < 2; ++q) {
                if (fminf(acc[q][0], acc[q][1]) < h0[KSEL - 1]) {
                    if (acc[q][0] < h0[KSEL - 1]) bubble_insert(h0, acc[q][0]);
                    if (acc[q][1] < h0[KSEL - 1]) bubble_insert(h0, acc[q][1]);
                }
                if (fminf(acc[q][2], acc[q][3]) < h1[KSEL - 1]) {
                    if (acc[q][2] < h1[KSEL - 1]) bubble_insert(h1, acc[q][2]);
                    if (acc[q][3] < h1[KSEL - 1]) bubble_insert(h1, acc[q][3]);
                }
            }

            // ---- SIMT co-path: 4 candidates per p on the FMA pipe ----
            if (sact) {
#pragma unroll 1
                for (int j = 0; j < 4; ++j) {
                    const int cc = p * 4 + j;
                    const uint32_t swz = (uint32_t)(cc & 7) << 4;
                    const uint32_t a = sb + (uint32_t)cc * 128;
                    uint32_t acc2 = 0;
                    {
                        uint4 b0 = *reinterpret_cast<const uint4*>(
                            (char*)0 + 0), b1;
                        // shared loads via inline address math (generic smem ptr)
                        b0 = *reinterpret_cast<const uint4*>(
                            smem + (a - sbase) + 0);   // placeholder (replaced below)
                        (void)b0; (void)b1;
                    }
                    // load 4x16B with swizzle-last XOR
                    const char* ap = smem + (a - sbase);
                    uint4 B0 = *reinterpret_cast<const uint4*>(ap + ((half64 +  0) ^ swz));
                    uint4 B1 = *reinterpret_cast<const uint4*>(ap + ((half64 + 16) ^ swz));
                    HFMA2BF(acc2, xs[0], B0.x); HFMA2BF(acc2, xs[1], B0.y);
                    HFMA2BF(acc2, xs[2], B0.z); HFMA2BF(acc2, xs[3], B0.w);
                    HFMA2BF(acc2, xs[4], B1.x); HFMA2BF(acc2, xs[5], B1.y);
                    HFMA2BF(acc2, xs[6], B1.z); HFMA2BF(acc2, xs[7], B1.w);
                    uint4 B2 = *reinterpret_cast<const uint4*>(ap + ((half64 + 32) ^ swz));
                    uint4 B3 = *reinterpret_cast<const uint4*>(ap + ((half64 + 48) ^ swz));
                    HFMA2BF(acc2, xs[8],  B2.x); HFMA2BF(acc2, xs[9],  B2.y);
                    HFMA2BF(acc2, xs[10], B2.z); HFMA2BF(acc2, xs[11], B2.w);
                    HFMA2BF(acc2, xs[12], B3.x); HFMA2BF(acc2, xs[13], B3.y);
                    HFMA2BF(acc2, xs[14], B3.z); HFMA2BF(acc2, xs[15], B3.w);
                    // horizontal: sum even/odd bf16 chains
                    uint32_t tsw;
                    asm("prmt.b32 %0, %1, %1, 0x1032;" : "=r"(tsw) : "r"(acc2));
                    uint32_t s2;
                    asm("add.rn.bf16x2 %0, %1, %2;" : "=r"(s2) : "r"(acc2), "r"(tsw));
                    float f = __uint_as_float(s2 << 16);     // -2*dot (partial)
                    f += __shfl_xor_sync(0xffffffffu, f, 1); // full -2*dot
                    if (tig == 0) {
                        float d = f + sbn[cc];
                        if (d < h0[KSEL - 1]) bubble_insert(h0, d);
                    } else if (tig == 2) {
                        float d = f + sbn[cc];
                        if (d < h1[KSEL - 1]) bubble_insert(h1, d);
                    }
                }
            }
        }
    }

    // ---- merge across the 4 tig lanes; tig 0 writes 1 list per row ----
    merge11(h0, 1); merge11(h0, 2);
    merge11(h1, 1); merge11(h1, 2);
    if (tig == 0) {
        float* p0 = &g_partial[((size_t)(row_base + g)     * MAXL + c) * KSEL];
        float* p1 = &g_partial[((size_t)(row_base + g + 8) * MAXL + c) * KSEL];
#pragma unroll
        for (int j = 0; j < KSEL; ++j) { p0[j] = h0[j]; p1[j] = h1[j]; }
    }
}

// ---------------- final merge kernel: one warp per row ----------------
__global__ void final_kernel(float* __restrict__ out) {
    const int row  = blockIdx.x * 8 + (threadIdx.x >> 5);
    const int lane = threadIdx.x & 31;
    const int nc   = (row < 4 * ROWS_CTA) ? 19 : 18;   // lists for this rowtile

    float h[KSEL];
    if (lane < nc) {
        const float* p = &g_partial[((size_t)row * MAXL + lane) * KSEL];
#pragma unroll
        for (int j = 0; j < KSEL; ++j) h[j] = p[j];
    } else {
#pragma unroll
        for (int j = 0; j < KSEL; ++j) h[j] = POS_INF;
    }
    merge11(h, 1); merge11(h, 2); merge11(h, 4); merge11(h, 8); merge11(h, 16);

    if (lane == 0) {
        float xn = g_xnorm[row];
        float s = 0.f;
#pragma unroll
        for (int j = 1; j < KSEL; ++j)          // drop self-match (h[0])
            s += sqrtf(fmaxf(xn + h[j], 0.f));
        out[row] = log1pf(s * (1.f / (KSEL - 1)));
    }
}

// ---------------- launch ----------------
extern "C" void kernel_launch(void* const* d_in, const int* in_sizes, int n_in,
                              void* d_out, int out_size) {
    const float* a = (const float*)d_in[0];
    const float* b = (const float*)d_in[1];
    const float* x = a;
    const float* buf = b;
    if (in_sizes[0] > in_sizes[1]) { x = b; buf = a; }

    cudaFuncSetAttribute(pbe_mma_kernel,
                         cudaFuncAttributeMaxDynamicSharedMemorySize, SMEM_TOTAL);

    prep_buf_kernel<<<M_CANDS / 256, 256>>>(buf);
    prep_x_kernel<<<N_ROWS / 256, 256>>>(x);

    pbe_mma_kernel<<<GRID_MAIN, THREADS, SMEM_TOTAL>>>();

    final_kernel<<<N_ROWS / 8, 256>>>((float*)d_out);
}

// round 15
// speedup vs baseline: 1.8966x; 1.8966x over previous
#include <cuda_runtime.h>
#include <cuda_fp16.h>
#include <cstdint>

// ---------------- problem constants ----------------
#define M_CANDS 131072
#define N_ROWS  2048
#define DIM     64
#define KSEL    11                 // k+1 smallest; smallest (self) dropped later

// ---------------- tiling / ragged static decomposition ----------------
#define ROWS_CTA 256                     // x rows per CTA (16 warps x 16 rows)
#define ROWTILES (N_ROWS / ROWS_CTA)     // 8
#define TN       256                     // candidates per smem tile
#define NTILES   (M_CANDS / TN)          // 512 tile-columns per rowtile
#define THREADS  512
#define GRID_MAIN 148                    // rowtiles 0-3: 19 CTAs, 4-7: 18 CTAs
#define MAXL     19                      // max lists per row
#define TILE_BYTES (TN * 128)            // 32768 (f16, 128B per candidate)
#define BN_BYTES   (TN * 2)              // 512 (f16 norms)

// ---------------- smem layout (bytes) ----------------
#define SM_MBAR  0                       // 3 mbarriers
#define SM_B     1024
#define SM_BN    (SM_B + 3 * TILE_BYTES)          // 99328
#define SMEM_TOTAL (SM_BN + 3 * BN_BYTES)         // 100864

#define POS_INF __int_as_float(0x7f800000)
#define NEG_INF __int_as_float(0xff800000)

// ---------------- device globals (allocation-free scratch) ----------------
__device__ __align__(128) __half g_bh[(size_t)M_CANDS * DIM];   // -2*buf, f16, tile-swizzled
__device__ __align__(16)  __half g_xh[(size_t)N_ROWS * DIM];    // x, f16, row-major
__device__ __align__(16)  __half g_bnh[M_CANDS];                // |b|^2, f16
__device__ __align__(16)  float  g_xnorm[N_ROWS];               // |x|^2, fp32 exact
__device__ __align__(16)  float  g_partial[(size_t)N_ROWS * MAXL * KSEL];

// ---------------- helpers ----------------
__device__ __forceinline__ uint32_t smem_u32(const void* p) {
    return (uint32_t)__cvta_generic_to_shared(p);
}
#define SWZ128(off) ((off) ^ (((off) >> 3) & 0x70))

#define MBARRIER_INIT(mbar, cnt) \
    asm volatile("mbarrier.init.shared.b64 [%0], %1;" \
                 :: "r"((uint32_t)(mbar)), "r"((uint32_t)(cnt)) : "memory")
#define MBARRIER_EXPECT_TX(mbar, bytes) \
    asm volatile("mbarrier.arrive.expect_tx.shared.b64 _, [%0], %1;" \
                 :: "r"((uint32_t)(mbar)), "r"((uint32_t)(bytes)) : "memory")
#define MBARRIER_WAIT_PARITY(mbar, parity) do {                                   \
    uint32_t _m = (uint32_t)(mbar); uint32_t _p = (uint32_t)(parity);             \
    asm volatile("{\n\t.reg .pred P1;\n\t"                                        \
        "WAIT_LOOP_%=:\n\t"                                                       \
        "mbarrier.try_wait.parity.acquire.cta.shared::cta.b64 P1, [%0], %1, 0x989680;\n\t" \
        "@P1 bra.uni WAIT_DONE_%=;\n\t"                                           \
        "bra.uni WAIT_LOOP_%=;\n\t"                                               \
        "WAIT_DONE_%=:\n\t}" :: "r"(_m), "r"(_p) : "memory");                     \
} while (0)

__device__ __forceinline__ void bulk_g2s(uint32_t dst, const void* src,
                                         uint32_t bytes, uint32_t mbar) {
    asm volatile(
        "cp.async.bulk.shared::cluster.global.mbarrier::complete_tx::bytes "
        "[%0], [%1], %2, [%3];"
        :: "r"(dst), "l"(__cvta_generic_to_global(src)), "r"(bytes), "r"(mbar)
        : "memory");
}

// ldmatrix x4: 4 8x8 b16 matrices; lane supplies one 16B row address
__device__ __forceinline__ void ldsm4(uint32_t* r, uint32_t addr) {
    asm volatile("ldmatrix.sync.aligned.m8n8.x4.shared.b16 {%0,%1,%2,%3}, [%4];"
                 : "=r"(r[0]), "=r"(r[1]), "=r"(r[2]), "=r"(r[3]) : "r"(addr));
}

// m16n8k16 row.col f16 -> f16 (fp16 accumulate), D += A*B (D aliases C, packed)
__device__ __forceinline__ void mma16816h(uint32_t c[2], const uint32_t a[4],
                                          uint32_t b0, uint32_t b1) {
    asm volatile(
        "mma.sync.aligned.m16n8k16.row.col.f16.f16.f16.f16 "
        "{%0,%1}, {%2,%3,%4,%5}, {%6,%7}, {%0,%1};"
        : "+r"(c[0]), "+r"(c[1])
        : "r"(a[0]), "r"(a[1]), "r"(a[2]), "r"(a[3]), "r"(b0), "r"(b1));
}

// register-resident ascending insert; v > h[10] is a no-op
__device__ __forceinline__ void bubble_insert(float* h, float v) {
#pragma unroll
    for (int j = 0; j < KSEL; ++j) {
        float lo = fminf(h[j], v);
        v = fmaxf(h[j], v);
        h[j] = lo;
    }
}

// merge my ascending 11-list with lane^mask's; keep 11 smallest, ascending
__device__ __forceinline__ void merge11(float h[KSEL], int mask) {
    float b[KSEL];
#pragma unroll
    for (int j = 0; j < KSEL; ++j) b[j] = __shfl_xor_sync(0xffffffffu, h[j], mask);
    float c[16];
#pragma unroll
    for (int i = 0; i < 5; ++i) c[i] = NEG_INF;
#pragma unroll
    for (int i = 0; i < KSEL; ++i) c[5 + i] = fminf(h[i], b[10 - i]);
#pragma unroll
    for (int d = 8; d >= 1; d >>= 1)
#pragma unroll
        for (int i = 0; i < 16; ++i)
            if ((i & d) == 0) {
                float lo = fminf(c[i], c[i | d]);
                float hi = fmaxf(c[i], c[i | d]);
                c[i] = lo; c[i | d] = hi;
            }
#pragma unroll
    for (int i = 0; i < KSEL; ++i) h[i] = c[5 + i];
}

// ---------------- merged prep kernel ----------------
// blocks 0..511: quantize -2*buf -> f16 (tile-swizzled) + f16 |b|^2
// blocks 512..519: quantize x -> f16 + fp32 |x|^2
__global__ void prep_kernel(const float* __restrict__ buf,
                            const float* __restrict__ x) {
    if (blockIdx.x < 512) {
        int c = blockIdx.x * 256 + threadIdx.x;
        const float4* s = reinterpret_cast<const float4*>(buf) + (size_t)c * 16;
        uint4 pk[8];
        uint32_t* pw = reinterpret_cast<uint32_t*>(pk);
        float n = 0.f;
#pragma unroll
        for (int q = 0; q < 16; ++q) {
            float4 v = s[q];
            n = fmaf(v.x, v.x, n); n = fmaf(v.y, v.y, n);
            n = fmaf(v.z, v.z, n); n = fmaf(v.w, v.w, n);
            __half2 a = __floats2half2_rn(-2.f * v.x, -2.f * v.y);
            __half2 b = __floats2half2_rn(-2.f * v.z, -2.f * v.w);
            pw[2 * q]     = reinterpret_cast<uint32_t&>(a);
            pw[2 * q + 1] = reinterpret_cast<uint32_t&>(b);
        }
        char* blk = reinterpret_cast<char*>(g_bh) + (size_t)(c >> 8) * TILE_BYTES;
        uint32_t r = (uint32_t)(c & 255);
#pragma unroll
        for (int q = 0; q < 8; ++q)
            *reinterpret_cast<uint4*>(blk + SWZ128(r * 128 + q * 16)) = pk[q];
        g_bnh[c] = __float2half_rn(n);
    } else {
        int c = (blockIdx.x - 512) * 256 + threadIdx.x;
        const float4* s = reinterpret_cast<const float4*>(x) + (size_t)c * 16;
        uint4 pk[8];
        uint32_t* pw = reinterpret_cast<uint32_t*>(pk);
        float n = 0.f;
#pragma unroll
        for (int q = 0; q < 16; ++q) {
            float4 v = s[q];
            n = fmaf(v.x, v.x, n); n = fmaf(v.y, v.y, n);
            n = fmaf(v.z, v.z, n); n = fmaf(v.w, v.w, n);
            __half2 a = __floats2half2_rn(v.x, v.y);
            __half2 b = __floats2half2_rn(v.z, v.w);
            pw[2 * q]     = reinterpret_cast<uint32_t&>(a);
            pw[2 * q + 1] = reinterpret_cast<uint32_t&>(b);
        }
        uint4* dst = reinterpret_cast<uint4*>(g_xh) + (size_t)c * 8;
#pragma unroll
        for (int i = 0; i < 8; ++i) dst[i] = pk[i];
        g_xnorm[c] = n;
    }
}

// ---------------- main fused GEMM + top-k kernel (single unit per CTA) ----
extern __shared__ char smem[];

__global__ void __launch_bounds__(THREADS, 1)
pbe_mma_kernel() {
    const int tid  = threadIdx.x;
    const int lane = tid & 31;
    const int w    = tid >> 5;           // 0..15
    const int g    = lane >> 2;          // 0..7
    const int tig  = lane & 3;           // 0..3

    // ---- ragged static assignment: (rowtile, contiguous tile range) ----
    int rt, c, nc;
    {
        const int b = blockIdx.x;        // 0..147
        if (b < 76) { rt = b / 19; c = b - rt * 19; nc = 19; }
        else { int b2 = b - 76; rt = 4 + b2 / 18; c = b2 - (rt - 4) * 18; nc = 18; }
    }
    const int t0 = (NTILES * c) / nc;
    const int nt = (NTILES * (c + 1)) / nc - t0;   // 26..29 tiles
    const int row_base = rt * ROWS_CTA + w * 16;

    const uint32_t sbase = smem_u32(smem);
    const uint32_t mb0   = sbase + SM_MBAR;

    // ---- A fragments: 1 m-block (16 rows) per warp, persistent ----
    uint32_t afr[4][4];
    {
        const uint32_t* x0 = reinterpret_cast<const uint32_t*>(
            g_xh + (size_t)(row_base + g) * DIM);
        const uint32_t* x1 = reinterpret_cast<const uint32_t*>(
            g_xh + (size_t)(row_base + g + 8) * DIM);
#pragma unroll
        for (int kc = 0; kc < 4; ++kc) {
            afr[kc][0] = x0[kc * 8 + tig];
            afr[kc][1] = x1[kc * 8 + tig];
            afr[kc][2] = x0[kc * 8 + tig + 4];
            afr[kc][3] = x1[kc * 8 + tig + 4];
        }
    }

    // ---- per-lane ldmatrix offsets (swizzle XOR applied last, no carries) ----
    const uint32_t l8  = (uint32_t)(lane & 7);
    const uint32_t qof = (uint32_t)((lane >> 3) * 16);
    const uint32_t sw  = l8 << 4;
    const uint32_t lm_off0 = l8 * 128 + (qof ^ sw);          // k bytes 0..63
    const uint32_t lm_off1 = l8 * 128 + ((qof + 64) ^ sw);   // k bytes 64..127

    // ---- mbarriers + prologue staging ----
    if (tid == 0) {
        MBARRIER_INIT(mb0 + 0,  1);
        MBARRIER_INIT(mb0 + 8,  1);
        MBARRIER_INIT(mb0 + 16, 1);
    }
    __syncthreads();

    auto issue = [&](int t) {            // thread 0 only
        int s = t % 3;
        uint32_t bar = mb0 + s * 8;
        uint32_t cb = (uint32_t)(t0 + t) * TN;   // candidate index
        MBARRIER_EXPECT_TX(bar, TILE_BYTES + BN_BYTES);
        bulk_g2s(sbase + SM_B + s * TILE_BYTES,
                 reinterpret_cast<const char*>(g_bh) + (size_t)cb * 128,
                 TILE_BYTES, bar);
        bulk_g2s(sbase + SM_BN + s * BN_BYTES, g_bnh + cb, BN_BYTES, bar);
    };
    if (tid == 0) { issue(0); issue(1); }

    // ---- top-11 lists for this thread's 2 rows ----
    float h0[KSEL], h1[KSEL];
#pragma unroll
    for (int j = 0; j < KSEL; ++j) { h0[j] = POS_INF; h1[j] = POS_INF; }

    uint32_t ph[3] = {0, 0, 0};

    for (int t = 0; t < nt; ++t) {
        const int slot = t % 3;
        __syncthreads();                 // all warps finished compute(t-1)
        if (t + 2 < nt && tid == 0) issue(t + 2);
        MBARRIER_WAIT_PARITY(mb0 + slot * 8, ph[slot]);
        ph[slot] ^= 1;

        const uint32_t tb0 = sbase + SM_B + slot * TILE_BYTES + lm_off0;
        const uint32_t tb1 = sbase + SM_B + slot * TILE_BYTES + lm_off1;
        // packed f16 norm pairs: uint32 at (nb*8 + tig*2)*2 bytes
        const uint32_t* bns = reinterpret_cast<const uint32_t*>(
            smem + SM_BN + slot * BN_BYTES) + tig;   // word index tig within nb-group

        uint32_t fA[2][8], fB[2][8];
        auto load_pair = [&](int p, uint32_t f[2][8]) {
            const uint32_t po = (uint32_t)(p * 2048);
            ldsm4(&f[0][0], tb0 + po);               // nb=2p,   k 0..31
            ldsm4(&f[0][4], tb1 + po);               // nb=2p,   k 32..63
            ldsm4(&f[1][0], tb0 + po + 1024);        // nb=2p+1, k 0..31
            ldsm4(&f[1][4], tb1 + po + 1024);        // nb=2p+1, k 32..63
        };
        load_pair(0, fA);

#pragma unroll
        for (int p = 0; p < 16; ++p) {
            uint32_t (*fc)[8] = (p & 1) ? fB : fA;
            uint32_t (*fn)[8] = (p & 1) ? fA : fB;
            if (p < 15) load_pair(p + 1, fn);

            // acc: packed f16x2; [q][0] = row g cols(2tig,2tig+1), [q][1] = row g+8
            uint32_t acc[2][2];
#pragma unroll
            for (int q = 0; q < 2; ++q) {
                uint32_t bnp = bns[(p * 2 + q) * 4];   // packed f16 norm pair
                acc[q][0] = bnp;
                acc[q][1] = bnp;
            }
#pragma unroll
            for (int kc = 0; kc < 4; ++kc) {
                mma16816h(acc[0], afr[kc], fc[0][kc * 2], fc[0][kc * 2 + 1]);
                mma16816h(acc[1], afr[kc], fc[1][kc * 2], fc[1][kc * 2 + 1]);
            }
            // acc IS the distance (bn - 2*dot) in f16; |x|^2 deferred
#pragma unroll
            for (int q = 0; q < 2; ++q) {
                float2 v0 = __half22float2(
                    *reinterpret_cast<const __half2*>(&acc[q][0]));
                float2 v1 = __half22float2(
                    *reinterpret_cast<const __half2*>(&acc[q][1]));
                if (fminf(v0.x, v0.y) < h0[KSEL - 1]) {
                    if (v0.x < h0[KSEL - 1]) bubble_insert(h0, v0.x);
                    if (v0.y < h0[KSEL - 1]) bubble_insert(h0, v0.y);
                }
                if (fminf(v1.x, v1.y) < h1[KSEL - 1]) {
                    if (v1.x < h1[KSEL - 1]) bubble_insert(h1, v1.x);
                    if (v1.y < h1[KSEL - 1]) bubble_insert(h1, v1.y);
                }
            }
        }
    }

    // ---- merge across the 4 tig lanes; tig 0 writes 1 list per row ----
    merge11(h0, 1); merge11(h0, 2);
    merge11(h1, 1); merge11(h1, 2);
    if (tig == 0) {
        float* p0 = &g_partial[((size_t)(row_base + g)     * MAXL + c) * KSEL];
        float* p1 = &g_partial[((size_t)(row_base + g + 8) * MAXL + c) * KSEL];
#pragma unroll
        for (int j = 0; j < KSEL; ++j) { p0[j] = h0[j]; p1[j] = h1[j]; }
    }
}

// ---------------- final merge kernel: one warp per row ----------------
__global__ void final_kernel(float* __restrict__ out) {
    const int row  = blockIdx.x * 8 + (threadIdx.x >> 5);
    const int lane = threadIdx.x & 31;
    const int nc   = (row < 4 * ROWS_CTA) ? 19 : 18;   // lists for this rowtile

    float h[KSEL];
    if (lane < nc) {
        const float* p = &g_partial[((size_t)row * MAXL + lane) * KSEL];
#pragma unroll
        for (int j = 0; j < KSEL; ++j) h[j] = p[j];
    } else {
#pragma unroll
        for (int j = 0; j < KSEL; ++j) h[j] = POS_INF;
    }
    merge11(h, 1); merge11(h, 2); merge11(h, 4); merge11(h, 8); merge11(h, 16);

    if (lane == 0) {
        float xn = g_xnorm[row];
        float s = 0.f;
#pragma unroll
        for (int j = 1; j < KSEL; ++j)          // drop self-match (h[0])
            s += sqrtf(fmaxf(xn + h[j], 0.f));
        out[row] = log1pf(s * (1.f / (KSEL - 1)));
    }
}

// ---------------- launch ----------------
extern "C" void kernel_launch(void* const* d_in, const int* in_sizes, int n_in,
                              void* d_out, int out_size) {
    const float* a = (const float*)d_in[0];
    const float* b = (const float*)d_in[1];
    const float* x = a;
    const float* buf = b;
    if (in_sizes[0] > in_sizes[1]) { x = b; buf = a; }

    cudaFuncSetAttribute(pbe_mma_kernel,
                         cudaFuncAttributeMaxDynamicSharedMemorySize, SMEM_TOTAL);

    prep_kernel<<<520, 256>>>(buf, x);

    pbe_mma_kernel<<<GRID_MAIN, THREADS, SMEM_TOTAL>>>();

    final_kernel<<<N_ROWS / 8, 256>>>((float*)d_out);
}

// round 17
// speedup vs baseline: 2.0105x; 1.0601x over previous
#include <cuda_runtime.h>
#include <cuda_fp16.h>
#include <cstdint>

// ---------------- problem constants ----------------
#define M_CANDS 131072
#define N_ROWS  2048
#define DIM     64
#define KSEL    11                 // k+1 smallest; smallest (self) dropped later

// ---------------- tiling / static decomposition ----------------
#define ROWS_CTA 256                     // x rows per CTA (16 warps x 16 rows)
#define ROWTILES (N_ROWS / ROWS_CTA)     // 8
#define TN       256                     // candidates per smem tile
#define NTILES   (M_CANDS / TN)          // 512 tile-columns per rowtile
#define THREADS  512
#define MAXL     19                      // max lists per row
#define TILE_BYTES (TN * 128)            // 32768 (f16, 128B per candidate)
#define BN_BYTES   (TN * 2)              // 512 (f16 norms)

// ---------------- smem layout (bytes) ----------------
#define SM_MBAR  0                       // 3 mbarriers
#define SM_B     1024
#define SM_BN    (SM_B + 3 * TILE_BYTES)          // 99328
#define SMEM_TOTAL (SM_BN + 3 * BN_BYTES)         // 100864

#define POS_INF __int_as_float(0x7f800000)
#define NEG_INF __int_as_float(0xff800000)

// ---------------- device globals (allocation-free scratch) ----------------
__device__ __align__(128) __half g_bh[(size_t)M_CANDS * DIM];   // -2*buf, f16, tile-swizzled
__device__ __align__(16)  __half g_xh[(size_t)N_ROWS * DIM];    // x, f16, row-major
__device__ __align__(16)  __half g_bnh[M_CANDS];                // |b|^2, f16
__device__ __align__(16)  float  g_xnorm[N_ROWS];               // |x|^2, fp32 exact
__device__ __align__(16)  float  g_partial[(size_t)N_ROWS * MAXL * KSEL];

// ---------------- helpers ----------------
__device__ __forceinline__ uint32_t smem_u32(const void* p) {
    return (uint32_t)__cvta_generic_to_shared(p);
}
#define SWZ128(off) ((off) ^ (((off) >> 3) & 0x70))

#define MBARRIER_INIT(mbar, cnt) \
    asm volatile("mbarrier.init.shared.b64 [%0], %1;" \
                 :: "r"((uint32_t)(mbar)), "r"((uint32_t)(cnt)) : "memory")
#define MBARRIER_EXPECT_TX(mbar, bytes) \
    asm volatile("mbarrier.arrive.expect_tx.shared.b64 _, [%0], %1;" \
                 :: "r"((uint32_t)(mbar)), "r"((uint32_t)(bytes)) : "memory")
#define MBARRIER_WAIT_PARITY(mbar, parity) do {                                   \
    uint32_t _m = (uint32_t)(mbar); uint32_t _p = (uint32_t)(parity);             \
    asm volatile("{\n\t.reg .pred P1;\n\t"                                        \
        "WAIT_LOOP_%=:\n\t"                                                       \
        "mbarrier.try_wait.parity.acquire.cta.shared::cta.b64 P1, [%0], %1, 0x989680;\n\t" \
        "@P1 bra.uni WAIT_DONE_%=;\n\t"                                           \
        "bra.uni WAIT_LOOP_%=;\n\t"                                               \
        "WAIT_DONE_%=:\n\t}" :: "r"(_m), "r"(_p) : "memory");                     \
} while (0)

__device__ __forceinline__ void bulk_g2s(uint32_t dst, const void* src,
                                         uint32_t bytes, uint32_t mbar) {
    asm volatile(
        "cp.async.bulk.shared::cluster.global.mbarrier::complete_tx::bytes "
        "[%0], [%1], %2, [%3];"
        :: "r"(dst), "l"(__cvta_generic_to_global(src)), "r"(bytes), "r"(mbar)
        : "memory");
}

// ldmatrix x4: 4 8x8 b16 matrices; lane supplies one 16B row address
__device__ __forceinline__ void ldsm4(uint32_t* r, uint32_t addr) {
    asm volatile("ldmatrix.sync.aligned.m8n8.x4.shared.b16 {%0,%1,%2,%3}, [%4];"
                 : "=r"(r[0]), "=r"(r[1]), "=r"(r[2]), "=r"(r[3]) : "r"(addr));
}

// m16n8k16 row.col f16 -> f16 (fp16 accumulate), D += A*B (D aliases C, packed)
__device__ __forceinline__ void mma16816h(uint32_t c[2], const uint32_t a[4],
                                          uint32_t b0, uint32_t b1) {
    asm volatile(
        "mma.sync.aligned.m16n8k16.row.col.f16.f16.f16.f16 "
        "{%0,%1}, {%2,%3,%4,%5}, {%6,%7}, {%0,%1};"
        : "+r"(c[0]), "+r"(c[1])
        : "r"(a[0]), "r"(a[1]), "r"(a[2]), "r"(a[3]), "r"(b0), "r"(b1));
}

// register-resident ascending insert; v > h[10] is a no-op
__device__ __forceinline__ void bubble_insert(float* h, float v) {
#pragma unroll
    for (int j = 0; j < KSEL; ++j) {
        float lo = fminf(h[j], v);
        v = fmaxf(h[j], v);
        h[j] = lo;
    }
}

// merge my ascending 11-list with lane^mask's; keep 11 smallest, ascending
__device__ __forceinline__ void merge11(float h[KSEL], int mask) {
    float b[KSEL];
#pragma unroll
    for (int j = 0; j < KSEL; ++j) b[j] = __shfl_xor_sync(0xffffffffu, h[j], mask);
    float c[16];
#pragma unroll
    for (int i = 0; i < 5; ++i) c[i] = NEG_INF;
#pragma unroll
    for (int i = 0; i < KSEL; ++i) c[5 + i] = fminf(h[i], b[10 - i]);
#pragma unroll
    for (int d = 8; d >= 1; d >>= 1)
#pragma unroll
        for (int i = 0; i < 16; ++i)
            if ((i & d) == 0) {
                float lo = fminf(c[i], c[i | d]);
                float hi = fmaxf(c[i], c[i | d]);
                c[i] = lo; c[i | d] = hi;
            }
#pragma unroll
    for (int i = 0; i < KSEL; ++i) h[i] = c[5 + i];
}

// ---------------- merged prep kernel (coalesced) ----------------
// blocks 0..511: one 256-cand tile each. Each warp covers 32 cands
// (2 per round x 16 rounds; 16 lanes per cand). Coalesced 256B-segment
// reads, cand-major f16 staging in smem, swizzle applied as GATHER on the
// write side -> pure coalesced STG.128. f16 |b|^2 via 16-lane shfl reduce.
// blocks 512..519: quantize x -> f16 + fp32 |x|^2.
__global__ void prep_kernel(const float* __restrict__ buf,
                            const float* __restrict__ x) {
    if (blockIdx.x < 512) {
        __shared__ uint32_t swv[8192];           // 256 cands x 32 words (32 KB)
        const int tid  = threadIdx.x;
        const int lane = tid & 31;
        const int w    = tid >> 5;               // warp: 32 cands
        const int cl   = lane >> 4;              // 0..1 (cand within round)
        const int q    = lane & 15;              // float4 index within row
#pragma unroll
        for (int r = 0; r < 16; ++r) {
            const int cand = w * 32 + r * 2 + cl; // local cand 0..255
            const float4 v = reinterpret_cast<const float4*>(buf)
                [((size_t)blockIdx.x * 256 + cand) * 16 + q];
            float n = v.x * v.x + v.y * v.y;
            n = fmaf(v.z, v.z, n); n = fmaf(v.w, v.w, n);
            __half2 a = __floats2half2_rn(-2.f * v.x, -2.f * v.y);
            __half2 b = __floats2half2_rn(-2.f * v.z, -2.f * v.w);
            swv[cand * 32 + q * 2]     = reinterpret_cast<uint32_t&>(a);
            swv[cand * 32 + q * 2 + 1] = reinterpret_cast<uint32_t&>(b);
            // reduce |b|^2 over the 16 lanes of this cand
            n += __shfl_xor_sync(0xffffffffu, n, 1);
            n += __shfl_xor_sync(0xffffffffu, n, 2);
            n += __shfl_xor_sync(0xffffffffu, n, 4);
            n += __shfl_xor_sync(0xffffffffu, n, 8);
            if (q == 0)
                g_bnh[(size_t)blockIdx.x * 256 + cand] = __float2half_rn(n);
        }
        __syncthreads();
        uint4* dst = reinterpret_cast<uint4*>(
            reinterpret_cast<char*>(g_bh) + (size_t)blockIdx.x * TILE_BYTES);
#pragma unroll
        for (int i = 0; i < 8; ++i) {
            const int idx = tid + i * 256;               // 16B chunk index
            const uint32_t s = SWZ128((uint32_t)(idx * 16)) >> 2;
            uint4 o;
            o.x = swv[s]; o.y = swv[s + 1]; o.z = swv[s + 2]; o.w = swv[s + 3];
            dst[idx] = o;                                 // coalesced
        }
    } else {
        int c = (blockIdx.x - 512) * 256 + threadIdx.x;
        const float4* s = reinterpret_cast<const float4*>(x) + (size_t)c * 16;
        uint4 pk[8];
        uint32_t* pw = reinterpret_cast<uint32_t*>(pk);
        float n = 0.f;
#pragma unroll
        for (int q = 0; q < 16; ++q) {
            float4 v = s[q];
            n = fmaf(v.x, v.x, n); n = fmaf(v.y, v.y, n);
            n = fmaf(v.z, v.z, n); n = fmaf(v.w, v.w, n);
            __half2 a = __floats2half2_rn(v.x, v.y);
            __half2 b = __floats2half2_rn(v.z, v.w);
            pw[2 * q]     = reinterpret_cast<uint32_t&>(a);
            pw[2 * q + 1] = reinterpret_cast<uint32_t&>(b);
        }
        uint4* dst = reinterpret_cast<uint4*>(g_xh) + (size_t)c * 8;
#pragma unroll
        for (int i = 0; i < 8; ++i) dst[i] = pk[i];
        g_xnorm[c] = n;
    }
}

// ---------------- main fused GEMM + top-k kernel (single unit per CTA) ----
extern __shared__ char smem[];

__global__ void __launch_bounds__(THREADS, 1)
pbe_mma_kernel(int n0, int n1) {       // CTAs per rowtile: rowtiles 0-3 / 4-7
    const int tid  = threadIdx.x;
    const int lane = tid & 31;
    const int w    = tid >> 5;           // 0..15
    const int g    = lane >> 2;          // 0..7
    const int tig  = lane & 3;           // 0..3

    // ---- static assignment: (rowtile, contiguous tile range) ----
    int rt, c, nc;
    {
        const int b = blockIdx.x;
        if (b < 4 * n0) { rt = b / n0; c = b - rt * n0; nc = n0; }
        else { int b2 = b - 4 * n0; rt = 4 + b2 / n1; c = b2 - (rt - 4) * n1; nc = n1; }
    }
    const int t0 = (NTILES * c) / nc;
    const int nt = (NTILES * (c + 1)) / nc - t0;
    const int row_base = rt * ROWS_CTA + w * 16;

    const uint32_t sbase = smem_u32(smem);
    const uint32_t mb0   = sbase + SM_MBAR;

    // ---- A fragments: 1 m-block (16 rows) per warp, persistent ----
    uint32_t afr[4][4];
    {
        const uint32_t* x0 = reinterpret_cast<const uint32_t*>(
            g_xh + (size_t)(row_base + g) * DIM);
        const uint32_t* x1 = reinterpret_cast<const uint32_t*>(
            g_xh + (size_t)(row_base + g + 8) * DIM);
#pragma unroll
        for (int kc = 0; kc < 4; ++kc) {
            afr[kc][0] = x0[kc * 8 + tig];
            afr[kc][1] = x1[kc * 8 + tig];
            afr[kc][2] = x0[kc * 8 + tig + 4];
            afr[kc][3] = x1[kc * 8 + tig + 4];
        }
    }

    // ---- per-lane ldmatrix offsets (swizzle XOR applied last, no carries) ----
    const uint32_t l8  = (uint32_t)(lane & 7);
    const uint32_t qof = (uint32_t)((lane >> 3) * 16);
    const uint32_t sw  = l8 << 4;
    const uint32_t lm_off0 = l8 * 128 + (qof ^ sw);          // k bytes 0..63
    const uint32_t lm_off1 = l8 * 128 + ((qof + 64) ^ sw);   // k bytes 64..127

    // ---- mbarriers + prologue staging ----
    if (tid == 0) {
        MBARRIER_INIT(mb0 + 0,  1);
        MBARRIER_INIT(mb0 + 8,  1);
        MBARRIER_INIT(mb0 + 16, 1);
    }
    __syncthreads();

    auto issue = [&](int t) {            // thread 0 only
        int s = t % 3;
        uint32_t bar = mb0 + s * 8;
        uint32_t cb = (uint32_t)(t0 + t) * TN;   // candidate index
        MBARRIER_EXPECT_TX(bar, TILE_BYTES + BN_BYTES);
        bulk_g2s(sbase + SM_B + s * TILE_BYTES,
                 reinterpret_cast<const char*>(g_bh) + (size_t)cb * 128,
                 TILE_BYTES, bar);
        bulk_g2s(sbase + SM_BN + s * BN_BYTES, g_bnh + cb, BN_BYTES, bar);
    };
    if (tid == 0) { issue(0); issue(1); }

    // ---- top-11 lists for this thread's 2 rows ----
    float h0[KSEL], h1[KSEL];
#pragma unroll
    for (int j = 0; j < KSEL; ++j) { h0[j] = POS_INF; h1[j] = POS_INF; }

    uint32_t ph[3] = {0, 0, 0};

    for (int t = 0; t < nt; ++t) {
        const int slot = t % 3;
        __syncthreads();                 // all warps finished compute(t-1)
        if (t + 2 < nt && tid == 0) issue(t + 2);
        MBARRIER_WAIT_PARITY(mb0 + slot * 8, ph[slot]);
        ph[slot] ^= 1;

        const uint32_t tb0 = sbase + SM_B + slot * TILE_BYTES + lm_off0;
        const uint32_t tb1 = sbase + SM_B + slot * TILE_BYTES + lm_off1;
        const uint32_t* bns = reinterpret_cast<const uint32_t*>(
            smem + SM_BN + slot * BN_BYTES) + tig;

        uint32_t fA[2][8], fB[2][8];
        auto load_pair = [&](int p, uint32_t f[2][8]) {
            const uint32_t po = (uint32_t)(p * 2048);
            ldsm4(&f[0][0], tb0 + po);               // nb=2p,   k 0..31
            ldsm4(&f[0][4], tb1 + po);               // nb=2p,   k 32..63
            ldsm4(&f[1][0], tb0 + po + 1024);        // nb=2p+1, k 0..31
            ldsm4(&f[1][4], tb1 + po + 1024);        // nb=2p+1, k 32..63
        };
        load_pair(0, fA);

#pragma unroll
        for (int p = 0; p < 16; ++p) {
            uint32_t (*fc)[8] = (p & 1) ? fB : fA;
            uint32_t (*fn)[8] = (p & 1) ? fA : fB;
            if (p < 15) load_pair(p + 1, fn);

            // acc: packed f16x2; [q][0] = row g cols(2tig,2tig+1), [q][1] = row g+8
            uint32_t acc[2][2];
#pragma unroll
            for (int q = 0; q < 2; ++q) {
                uint32_t bnp = bns[(p * 2 + q) * 4];   // packed f16 norm pair
                acc[q][0] = bnp;
                acc[q][1] = bnp;
            }
#pragma unroll
            for (int kc = 0; kc < 4; ++kc) {
                mma16816h(acc[0], afr[kc], fc[0][kc * 2], fc[0][kc * 2 + 1]);
                mma16816h(acc[1], afr[kc], fc[1][kc * 2], fc[1][kc * 2 + 1]);
            }
            // acc IS the distance (bn - 2*dot) in f16; |x|^2 deferred
#pragma unroll
            for (int q = 0; q < 2; ++q) {
                float2 v0 = __half22float2(
                    *reinterpret_cast<const __half2*>(&acc[q][0]));
                float2 v1 = __half22float2(
                    *reinterpret_cast<const __half2*>(&acc[q][1]));
                if (fminf(v0.x, v0.y) < h0[KSEL - 1]) {
                    if (v0.x < h0[KSEL - 1]) bubble_insert(h0, v0.x);
                    if (v0.y < h0[KSEL - 1]) bubble_insert(h0, v0.y);
                }
                if (fminf(v1.x, v1.y) < h1[KSEL - 1]) {
                    if (v1.x < h1[KSEL - 1]) bubble_insert(h1, v1.x);
                    if (v1.y < h1[KSEL - 1]) bubble_insert(h1, v1.y);
                }
            }
        }
    }

    // ---- merge across the 4 tig lanes; tig 0 writes 1 list per row ----
    merge11(h0, 1); merge11(h0, 2);
    merge11(h1, 1); merge11(h1, 2);
    if (tig == 0) {
        float* p0 = &g_partial[((size_t)(row_base + g)     * MAXL + c) * KSEL];
        float* p1 = &g_partial[((size_t)(row_base + g + 8) * MAXL + c) * KSEL];
#pragma unroll
        for (int j = 0; j < KSEL; ++j) { p0[j] = h0[j]; p1[j] = h1[j]; }
    }
}

// ---------------- final merge kernel: one warp per row ----------------
__global__ void final_kernel(float* __restrict__ out, int n0, int n1) {
    const int row  = blockIdx.x * 8 + (threadIdx.x >> 5);
    const int lane = threadIdx.x & 31;
    const int nc   = (row < 4 * ROWS_CTA) ? n0 : n1;   // lists for this rowtile

    float h[KSEL];
    if (lane < nc) {
        const float* p = &g_partial[((size_t)row * MAXL + lane) * KSEL];
#pragma unroll
        for (int j = 0; j < KSEL; ++j) h[j] = p[j];
    } else {
#pragma unroll
        for (int j = 0; j < KSEL; ++j) h[j] = POS_INF;
    }
    merge11(h, 1); merge11(h, 2); merge11(h, 4); merge11(h, 8); merge11(h, 16);

    if (lane == 0) {
        float xn = g_xnorm[row];
        float s = 0.f;
#pragma unroll
        for (int j = 1; j < KSEL; ++j)          // drop self-match (h[0])
            s += sqrtf(fmaxf(xn + h[j], 0.f));
        out[row] = log1pf(s * (1.f / (KSEL - 1)));
    }
}

// ---------------- launch ----------------
extern "C" void kernel_launch(void* const* d_in, const int* in_sizes, int n_in,
                              void* d_out, int out_size) {
    const float* a = (const float*)d_in[0];
    const float* b = (const float*)d_in[1];
    const float* x = a;
    const float* buf = b;
    if (in_sizes[0] > in_sizes[1]) { x = b; buf = a; }

    // one-CTA-per-SM uniform split when the chip has >=152 SMs (GB300),
    // otherwise the proven 148-CTA ragged split (B300).
    int dev = 0, sms = 148;
    cudaGetDevice(&dev);
    cudaDeviceGetAttribute(&sms, cudaDevAttrMultiProcessorCount, dev);
    const int n0 = 19;
    const int n1 = (sms >= 152) ? 19 : 18;
    const int grid = 4 * n0 + 4 * n1;

    cudaFuncSetAttribute(pbe_mma_kernel,
                         cudaFuncAttributeMaxDynamicSharedMemorySize, SMEM_TOTAL);

    prep_kernel<<<520, 256>>>(buf, x);

    pbe_mma_kernel<<<grid, THREADS, SMEM_TOTAL>>>(n0, n1);

    final_kernel<<<N_ROWS / 8, 256>>>((float*)d_out, n0, n1);
}